// round 9
// baseline (speedup 1.0000x reference)
#include <cuda_runtime.h>

// Problem constants (fixed by reference_code)
#define Bc 2
#define Nc 65536
#define Hc 128
#define Wc 128
#define HWc 16384
#define Gsplit 32              // split-K factor over gaussians
#define KN (Nc / Gsplit)       // 2048 gaussians per block range
#define KC 32                  // chunk of gaussians staged in smem
#define NTX 8                  // x tiles
#define NTY 8                  // y tiles
#define TDIMX 16
#define TDIMY 16
#define NTHR 128
#define NWARP (NTHR / 32)
#define NITER (KN / NTHR)      // 16 compaction rounds (2 batches of 8)
// cutoff: op*exp(a*d^2) <= e^-14 ~ 8.3e-7; validated rel_err ~9.3e-7 at R7.
#define CULL_LN (-14.0f)

// Scratch (static __device__ arrays — no allocation at runtime)
__device__ float4 g_params[Bc * Nc];                  // proj_x, proj_y, a=-0.5/var, opacity
__device__ float4 g_colop[Nc];                        // (op*cr, op*cg, op*cb, op)
__device__ float  g_part[Bc * Gsplit * 4 * HWc];      // split-K partials (r,g,b,den)

// ---------------------------------------------------------------------------
// Kernel 0: fold opacity into colors (camera-independent)
// ---------------------------------------------------------------------------
__global__ void k_colop(const float* __restrict__ colors,
                        const float* __restrict__ opa) {
    int n = blockIdx.x * blockDim.x + threadIdx.x;
    if (n >= Nc) return;
    float op = opa[n];
    g_colop[n] = make_float4(op * colors[3 * n], op * colors[3 * n + 1],
                             op * colors[3 * n + 2], op);
}

// ---------------------------------------------------------------------------
// Kernel 1: per-(camera, gaussian) projection parameters
// ---------------------------------------------------------------------------
__global__ void k_params(const float* __restrict__ pos,
                         const float* __restrict__ opa,
                         const float* __restrict__ scl,
                         const float* __restrict__ qv,
                         const float* __restrict__ tv,
                         const float* __restrict__ fx_,
                         const float* __restrict__ fy_,
                         const float* __restrict__ cx_,
                         const float* __restrict__ cy_) {
    int idx = blockIdx.x * blockDim.x + threadIdx.x;
    if (idx >= Bc * Nc) return;
    int b = idx >> 16;            // Nc = 65536
    int n = idx & (Nc - 1);

    float qw = qv[b * 4 + 0], qx = qv[b * 4 + 1], qy = qv[b * 4 + 2], qz = qv[b * 4 + 3];
    float inv = rsqrtf(qw * qw + qx * qx + qy * qy + qz * qz);
    qw *= inv; qx *= inv; qy *= inv; qz *= inv;

    float R00 = 1.f - 2.f * (qy * qy + qz * qz);
    float R01 = 2.f * (qx * qy - qz * qw);
    float R02 = 2.f * (qx * qz + qy * qw);
    float R10 = 2.f * (qx * qy + qz * qw);
    float R11 = 1.f - 2.f * (qx * qx + qz * qz);
    float R12 = 2.f * (qy * qz - qx * qw);
    float R20 = 2.f * (qx * qz - qy * qw);
    float R21 = 2.f * (qy * qz + qx * qw);
    float R22 = 1.f - 2.f * (qx * qx + qy * qy);

    float px = pos[3 * n], py = pos[3 * n + 1], pz = pos[3 * n + 2];
    // p_cam = positions @ R.T + t
    float cxm = R00 * px + R01 * py + R02 * pz + tv[b * 3 + 0];
    float cym = R10 * px + R11 * py + R12 * pz + tv[b * 3 + 1];
    float czm = R20 * px + R21 * py + R22 * pz + tv[b * 3 + 2];

    float projx = cxm / czm * fx_[0] + cx_[0];
    float projy = cym / czm * fy_[0] + cy_[0];
    float s = scl[n];
    float a = -0.5f / (s * s);

    g_params[idx] = make_float4(projx, projy, a, opa[n]);
}

// ---------------------------------------------------------------------------
// Kernel 2: culled separable splat, 16x16 tiles, 128-thread blocks.
//   grid = (32 splits, 64 tiles, 2 cams) = 4096 blocks.
//   Phase A: batched compaction — 2 prefetch batches of 8 LDG.128 (MLP=8),
//            ballot rounds with no mem waits, one BAR + register prefix.
//   Phase B: chunked rank-1 accumulation (KC=32, 4 staging slots/thread);
//            inner: LDS.64 + LDS.128 + 8 FFMA per gaussian per thread.
// ---------------------------------------------------------------------------
__global__ void __launch_bounds__(NTHR) k_splat() {
    __shared__ float  us[KC][TDIMX];        // 2 KB
    __shared__ float4 ds[KC][TDIMY];        // 8 KB
    __shared__ unsigned short list[KN];     // 4 KB
    __shared__ int cnts[NITER][NWARP];

    const int t    = threadIdx.x;
    const int g    = blockIdx.x;            // k-split index
    const int tile = blockIdx.y;            // 0..63
    const int b    = blockIdx.z;            // camera
    const int x0   = (tile & (NTX - 1)) * TDIMX;
    const int y0   = (tile / NTX) * TDIMY;
    const int kbase0 = g * KN;
    const int wid  = t >> 5, lane = t & 31;

    const float4* __restrict__ prm = &g_params[b * Nc];

    // ---------------- Phase A: batched deterministic compaction ------------
    const float xlo = (float)x0, xhi = (float)(x0 + TDIMX - 1);
    const float ylo = (float)y0, yhi = (float)(y0 + TDIMY - 1);
    unsigned msk[NITER];

#pragma unroll
    for (int batch = 0; batch < 2; batch++) {
        float4 pp[NITER / 2];
#pragma unroll
        for (int i = 0; i < NITER / 2; i++)
            pp[i] = prm[kbase0 + (batch * (NITER / 2) + i) * NTHR + t];
#pragma unroll
        for (int i = 0; i < NITER / 2; i++) {
            int ii = batch * (NITER / 2) + i;
            float ex = fmaxf(fmaxf(xlo - pp[i].x, pp[i].x - xhi), 0.0f);
            float ey = fmaxf(fmaxf(ylo - pp[i].y, pp[i].y - yhi), 0.0f);
            bool inc = pp[i].z * (ex * ex + ey * ey) >= CULL_LN;
            msk[ii] = __ballot_sync(0xffffffffu, inc);
            if (lane == 0) cnts[ii][wid] = __popc(msk[ii]);
        }
    }
    __syncthreads();

    // in-register exclusive prefix over (iter, warp) in k-order
    int pre[NITER];
    int run = 0;
#pragma unroll
    for (int i = 0; i < NITER; i++) {
#pragma unroll
        for (int w = 0; w < NWARP; w++) {
            if (w == wid) pre[i] = run;
            run += cnts[i][w];
        }
    }
    const int cnt = run;

#pragma unroll
    for (int i = 0; i < NITER; i++) {
        if ((msk[i] >> lane) & 1u)
            list[pre[i] + __popc(msk[i] & ((1u << lane) - 1u))] =
                (unsigned short)(i * NTHR + t);
    }
    __syncthreads();

    // ---------------- Phase B: chunked accumulation over the list ----------
    // thread -> 2x * 1y pixel micro-tile
    const int tx  = t & 7;                 // px base = x0 + 2*tx
    const int tyy = t >> 3;                // py = y0 + tyy (0..15)
    const int xu  = t & 15, ku0 = t >> 4;  // stage: 4 k per thread (k = ku0 + 8i)

    float acc[2][4];
#pragma unroll
    for (int xi = 0; xi < 2; xi++)
#pragma unroll
        for (int ch = 0; ch < 4; ch++) acc[xi][ch] = 0.f;

    for (int kb = 0; kb < cnt; kb += KC) {
        __syncthreads();   // previous chunk consumers done

        // ---- stage u: 32k x 16x (4 per thread)
#pragma unroll
        for (int i = 0; i < 4; i++) {
            int k = ku0 + i * 8;
            int kk = kb + k;
            float u = 0.f;
            if (kk < cnt) {
                int nl = kbase0 + (int)list[kk];
                float4 pr = prm[nl];
                float dx = (float)(x0 + xu) - pr.x;
                u = __expf(pr.z * dx * dx);
            }
            us[k][xu] = u;
        }
        // ---- stage d: 32k x 16y, one exp + one LDG.128 of folded colors
#pragma unroll
        for (int i = 0; i < 4; i++) {
            int k = ku0 + i * 8;
            int kk = kb + k;
            float4 dval = make_float4(0.f, 0.f, 0.f, 0.f);
            if (kk < cnt) {
                int nl = kbase0 + (int)list[kk];
                float4 pr = prm[nl];
                float4 co = g_colop[(int)list[kk] + kbase0 - b * 0];  // index n within camera range
                float dy = (float)(y0 + xu) - pr.y;   // xu == y-slot mapping
                float e  = __expf(pr.z * dy * dy);
                dval = make_float4(co.x * e, co.y * e, co.z * e, co.w * e);
            }
            ds[k][xu] = dval;
        }
        __syncthreads();

        // ---- inner accumulation: 8 FFMA + LDS.64 + LDS.128 per k per thread
#pragma unroll 16
        for (int k = 0; k < KC; k++) {
            float2 u2 = *reinterpret_cast<const float2*>(&us[k][tx * 2]);
            float4 d  = ds[k][tyy];
            acc[0][0] += u2.x * d.x;
            acc[0][1] += u2.x * d.y;
            acc[0][2] += u2.x * d.z;
            acc[0][3] += u2.x * d.w;
            acc[1][0] += u2.y * d.x;
            acc[1][1] += u2.y * d.y;
            acc[1][2] += u2.y * d.z;
            acc[1][3] += u2.y * d.w;
        }
    }

    // ---- write deterministic split-K partials (4x STG.64 per thread)
    const int base_bg = ((b * Gsplit + g) * 4) * HWc;
    const int pidx = (y0 + tyy) * Wc + x0 + tx * 2;
#pragma unroll
    for (int ch = 0; ch < 4; ch++) {
        float2 o = make_float2(acc[0][ch], acc[1][ch]);
        *reinterpret_cast<float2*>(&g_part[base_bg + ch * HWc + pidx]) = o;
    }
}

// ---------------------------------------------------------------------------
// Kernel 3: reduce split-K partials. Parallel over (camera, pixel, channel):
//   512 blocks x 256 threads; block = 64 pixels x 4 channels; den broadcast
//   via smem. Each thread: 32 independent LDGs (MLP=32), coalesced in p.
// ---------------------------------------------------------------------------
__global__ void __launch_bounds__(256) k_finalize(float* __restrict__ out) {
    __shared__ float den_s[64];

    const int blk   = blockIdx.x;            // 0..511
    const int b     = blk >> 8;               // 256 blocks per camera
    const int pbase = (blk & 255) * 64;
    const int t     = threadIdx.x;
    const int ch    = t >> 6;                  // 0..3
    const int poff  = t & 63;
    const int p     = pbase + poff;

    float acc = 0.f;
#pragma unroll
    for (int s = 0; s < Gsplit; s++)
        acc += g_part[((b * Gsplit + s) * 4 + ch) * HWc + p];

    if (ch == 3) den_s[poff] = acc + 32.0f * 1e-8f;  // + n_chunks(=32)*EPS
    __syncthreads();

    if (ch < 3) {
        float inv = 1.0f / fmaxf(den_s[poff], 1e-8f);
        out[(b * 3 + ch) * HWc + p] = acc * inv;
    }
}

// ---------------------------------------------------------------------------
extern "C" void kernel_launch(void* const* d_in, const int* in_sizes, int n_in,
                              void* d_out, int out_size) {
    const float* pos = (const float*)d_in[0];
    const float* col = (const float*)d_in[1];
    const float* opa = (const float*)d_in[2];
    const float* scl = (const float*)d_in[3];
    const float* qv  = (const float*)d_in[4];
    const float* tv  = (const float*)d_in[5];
    const float* fx  = (const float*)d_in[6];
    const float* fy  = (const float*)d_in[7];
    const float* cx  = (const float*)d_in[8];
    const float* cy  = (const float*)d_in[9];

    k_colop<<<Nc / 256, 256>>>(col, opa);
    k_params<<<(Bc * Nc) / 256, 256>>>(pos, opa, scl, qv, tv, fx, fy, cx, cy);

    dim3 grid(Gsplit, NTX * NTY, Bc);   // 32 * 64 * 2 = 4096 blocks
    k_splat<<<grid, NTHR>>>();

    k_finalize<<<(Bc * HWc) / 64, 256>>>((float*)d_out);
}